// round 15
// baseline (speedup 1.0000x reference)
#include <cuda_runtime.h>
#include <cuda_fp16.h>
#include <cstdint>

#define EE 8
#define TT 2048
#define DD 1024
#define HH 4096

// ---------------- packed half scratch (pre-swizzled 16KB [128 x 64h] blocks) ---
__device__ __align__(1024) __half g_A1p[(size_t)EE * TT * DD];
__device__ __align__(1024) __half g_B1p[(size_t)EE * HH * DD];
__device__ __align__(1024) __half g_Bgp[(size_t)EE * HH * DD];
__device__ __align__(1024) __half g_B2p[(size_t)EE * DD * HH];
__device__ __align__(1024) __half g_A2p[(size_t)EE * TT * HH];

__device__ int g_ctr1, g_ctr2;       // dynamic tile counters (reset by prep_a)

// ---------------- helpers ------------------------------------------------------
__device__ __forceinline__ uint32_t smem_u32(const void* p) {
    uint32_t a;
    asm("{ .reg .u64 t; cvta.to.shared.u64 t, %1; cvt.u32.u64 %0, t; }" : "=r"(a) : "l"(p));
    return a;
}
__device__ __forceinline__ uint32_t swz128(uint32_t o) { return o ^ ((o >> 3) & 0x70); }

__device__ __forceinline__ void mbar_init(uint32_t m, uint32_t c) {
    asm volatile("mbarrier.init.shared.b64 [%0], %1;" :: "r"(m), "r"(c) : "memory");
}
__device__ __forceinline__ void mbar_expect_tx(uint32_t m, uint32_t bytes) {
    asm volatile("mbarrier.arrive.expect_tx.shared.b64 _, [%0], %1;"
                 :: "r"(m), "r"(bytes) : "memory");
}
__device__ __forceinline__ void mbar_arrive(uint32_t m) {
    asm volatile("mbarrier.arrive.shared.b64 _, [%0];" :: "r"(m) : "memory");
}
__device__ __forceinline__ void mbar_wait(uint32_t m, uint32_t parity) {
    asm volatile(
        "{\n\t.reg .pred P;\n"
        "LW_%=:\n\t"
        "mbarrier.try_wait.parity.acquire.cta.shared::cta.b64 P, [%0], %1, 0x989680;\n\t"
        "@P bra.uni LD_%=;\n\t"
        "bra.uni LW_%=;\n"
        "LD_%=:\n\t}"
        :: "r"(m), "r"(parity) : "memory");
}
__device__ __forceinline__ void bulk_g2s(uint32_t dst, const void* src,
                                         uint32_t bytes, uint32_t mbar) {
    asm volatile(
        "cp.async.bulk.shared::cluster.global.mbarrier::complete_tx::bytes "
        "[%0], [%1], %2, [%3];"
        :: "r"(dst), "l"(src), "r"(bytes), "r"(mbar) : "memory");
}
#define FENCE_ASYNC() asm volatile("fence.proxy.async.shared::cta;" ::: "memory")

__device__ __forceinline__ void ldm_x4(uint32_t* r, uint32_t addr) {
    asm volatile("ldmatrix.sync.aligned.m8n8.x4.shared.b16 {%0,%1,%2,%3}, [%4];"
                 : "=r"(r[0]), "=r"(r[1]), "=r"(r[2]), "=r"(r[3]) : "r"(addr));
}
__device__ __forceinline__ void mma16(float* c, const uint32_t* a, const uint32_t* b) {
    asm volatile(
        "mma.sync.aligned.m16n8k16.row.col.f32.f16.f16.f32 "
        "{%0,%1,%2,%3}, {%4,%5,%6,%7}, {%8,%9}, {%0,%1,%2,%3};"
        : "+f"(c[0]), "+f"(c[1]), "+f"(c[2]), "+f"(c[3])
        : "r"(a[0]), "r"(a[1]), "r"(a[2]), "r"(a[3]), "r"(b[0]), "r"(b[1]));
}
__device__ __forceinline__ float my_silu(float g) { return g / (1.0f + __expf(-g)); }
__device__ __forceinline__ uint32_t h2u(__half2 h) { return *reinterpret_cast<uint32_t*>(&h); }

// ---------------- shared transpose tile body ------------------------------------
__device__ __forceinline__ void transpose_tile(const float* __restrict__ in,
                                               __half* __restrict__ out,
                                               int R, int C, int b, int tid,
                                               __half* tsm /* 128*66 halves */) {
    const int NTc = C >> 7, NKB = R >> 6;
    const int nt = b % NTc;
    const int kb = (b / NTc) % NKB;
    const int e  = b / (NTc * NKB);

    const float* ip = in + (size_t)e * R * C + (size_t)(kb * 64) * C + nt * 128;

    const int warp = tid >> 5, cl = tid & 31;
#pragma unroll
    for (int it = 0; it < 4; it++) {
        int kr = (warp + 8 * it) * 2;
        float4 v0 = *reinterpret_cast<const float4*>(ip + (size_t)kr * C + 4 * cl);
        float4 v1 = *reinterpret_cast<const float4*>(ip + (size_t)(kr + 1) * C + 4 * cl);
        const float* f0 = &v0.x;
        const float* f1 = &v1.x;
#pragma unroll
        for (int j = 0; j < 4; j++) {
            __half2 h = __floats2half2_rn(f0[j], f1[j]);
            *reinterpret_cast<__half2*>(&tsm[(4 * cl + j) * 66 + kr]) = h;
        }
    }
    __syncthreads();

    char* bp = (char*)(out + (((size_t)(e * NTc + nt) * NKB + kb) << 13));
    const int kc = tid & 7, nlb = tid >> 3;
#pragma unroll
    for (int it = 0; it < 4; it++) {
        int nl = nlb + 32 * it;
        const uint32_t* rowp = reinterpret_cast<const uint32_t*>(&tsm[nl * 66 + kc * 8]);
        uint4 u;
        u.x = rowp[0]; u.y = rowp[1]; u.z = rowp[2]; u.w = rowp[3];
        *reinterpret_cast<uint4*>(bp + swz128((uint32_t)(nl * 128 + kc * 16))) = u;
    }
}

// =================================================================================
// PREP A (critical path): pack x + transpose w1, wg + counter reset
// =================================================================================
#define PK_NX 16384
#define PK_NW 4096

__global__ void __launch_bounds__(256, 6)
prep_a_kernel(const float* __restrict__ x, const float* __restrict__ w1,
              const float* __restrict__ wg) {
    const int tid = threadIdx.x;
    int b = blockIdx.x;

    if (b == 0 && tid == 0) { g_ctr1 = 0; g_ctr2 = 0; }

    if (b < PK_NX) {                                   // ---- pack x ----
        size_t idx = ((size_t)b * 256 + tid) * 4;
        float4 v = *reinterpret_cast<const float4*>(x + idx);
        int d = (int)(idx & (DD - 1));
        int t = (int)((idx / DD) & (TT - 1));
        int e = (int)(idx / ((size_t)TT * DD));
        int mt = t >> 7, r = t & 127, bd = d >> 6, c = d & 63;
        char* blk = (char*)(g_A1p + (((size_t)(e * 16 + mt) * 16 + bd) << 13));
        uint2 u;
        u.x = h2u(__floats2half2_rn(v.x, v.y));
        u.y = h2u(__floats2half2_rn(v.z, v.w));
        *reinterpret_cast<uint2*>(blk + swz128((uint32_t)(r * 128 + c * 2))) = u;
        return;
    }

    __shared__ __half tsm[128 * 66];
    b -= PK_NX;
    if (b < PK_NW) transpose_tile(w1, g_B1p, DD, HH, b, tid, tsm);
    else           transpose_tile(wg, g_Bgp, DD, HH, b - PK_NW, tid, tsm);
}

// =================================================================================
// PREP B (overlapped with GEMM1): transpose w2
// =================================================================================
__global__ void __launch_bounds__(256, 6)
prep_b_kernel(const float* __restrict__ w2) {
    __shared__ __half tsm[128 * 66];
    transpose_tile(w2, g_B2p, HH, DD, blockIdx.x, threadIdx.x, tsm);
}

// =================================================================================
// GEMM1 fused (persistent + dynamic tiles + split barriers), OCCUPANCY 2.
// CTA tile 128x64 dual-plane, 128 thr (4 warps 2x2, warp 64x32). f16 m16n8k16.
// Kc=64 -> 16 stages/tile; 3-stage ring (32KB/stage), depth-2 prefetch.
// mbars: full[3] @ sb+0,8,16 (count 1); empty[3] @ sb+24,32,40 (count 128).
// =================================================================================
#define G1_STG_B 32768
#define G1_SMEM (1024 + 3 * G1_STG_B)
#define NT1 (EE * 16 * 64)          // 8192 tiles

__global__ void __launch_bounds__(128, 2)
gemm1_kernel(const float* __restrict__ bias1, const float* __restrict__ biasg) {
    extern __shared__ float sm[];
    __shared__ int sm_next;
    const uint32_t sb = smem_u32(sm);
    const int tid = threadIdx.x, wid = tid >> 5, lane = tid & 31;
    const int gid = lane >> 2, tig = lane & 3;
    const int wr = wid >> 1, wc = wid & 1;            // 2x2 warp grid, warp 64x32

    const int mq = lane >> 3, lr = lane & 7;
    const int rA = (mq & 1) * 8 + lr,  cA = (mq >> 1) * 16;
    const int rB = (mq >> 1) * 8 + lr, cB = (mq & 1) * 16;

    float ah[4][4][4] = {}, ag[4][4][4] = {};         // 128 acc regs

    auto fill = [&](int tile_, int stg, int fb) {
        const int e = tile_ >> 10, nt = (tile_ >> 4) & 63, mtt = tile_ & 15;
        const __half* aS  = g_A1p + (((size_t)(e * 16 + mtt) * 16 + stg) << 13);
        const size_t boff = (((size_t)(e * 32 + (nt >> 1)) * 16 + stg) << 13) + (nt & 1) * 4096;
        const __half* b1S = g_B1p + boff;
        const __half* bgS = g_Bgp + boff;
        const uint32_t mb = sb + (uint32_t)fb * 8;
        const uint32_t dst = sb + 1024 + (uint32_t)fb * G1_STG_B;
        mbar_expect_tx(mb, G1_STG_B);
        bulk_g2s(dst,          aS,  16384, mb);
        bulk_g2s(dst + 16384,  b1S, 8192, mb);
        bulk_g2s(dst + 24576,  bgS, 8192, mb);
    };

    if (tid == 0) {
#pragma unroll
        for (int b = 0; b < 3; b++) { mbar_init(sb + b * 8, 1); mbar_init(sb + 24 + b * 8, 128); }
        sm_next = atomicAdd(&g_ctr1, 1);
        FENCE_ASYNC();
    }
    __syncthreads();
    int tile = sm_next;
    __syncthreads();                                  // all read before tid0 rewrites

    int pnext = NT1;                                  // producer-only state (tid0)
    if (tid == 0 && tile < NT1) {
        mbar_wait(sb + 24, 1); fill(tile, 0, 0);      // fresh: passes
        mbar_wait(sb + 32, 1); fill(tile, 1, 1);
    }

    int gs = 0, cb = 0, cph = 0;
#pragma unroll 1
    while (tile < NT1) {
#pragma unroll 1
        for (int s = 0; s < 16; s++, gs++) {
            if (tid == 0) {
                if (s == 0) { pnext = atomicAdd(&g_ctr1, 1); sm_next = pnext; }
                int fs = s + 2;
                int ft = (fs >= 16) ? pnext : tile;
                if (ft < NT1) {
                    int fgs = gs + 2;
                    int fj = fgs / 3, fb = fgs - 3 * fj;
                    mbar_wait(sb + 24 + (uint32_t)fb * 8, (uint32_t)((fj & 1) ^ 1));
                    fill(ft, fs & 15, fb);
                }
            }
            const int cbuf = cb;
            mbar_wait(sb + (uint32_t)cbuf * 8, (uint32_t)cph);
            if (++cb == 3) { cb = 0; cph ^= 1; }

            const uint32_t dA  = sb + 1024 + (uint32_t)cbuf * G1_STG_B;
            const uint32_t dB1 = dA + 16384;
            const uint32_t dB2 = dA + 24576;

            uint32_t af[2][4][4], bf1[2][4][2], bf2[2][4][2];

            auto ldfr = [&](int ks, int pb) {
#pragma unroll
                for (int i = 0; i < 4; i++) {
                    int row = wr * 64 + i * 16 + rA;
                    uint32_t ad = dA + (uint32_t)row * 128
                                + (uint32_t)((ks * 32 + cA) ^ ((row & 7) << 4));
                    ldm_x4(af[pb][i], ad);
                }
#pragma unroll
                for (int jp = 0; jp < 2; jp++) {
                    int n = wc * 32 + jp * 16 + rB;
                    uint32_t off = (uint32_t)n * 128
                                 + (uint32_t)((ks * 32 + cB) ^ ((n & 7) << 4));
                    ldm_x4(&bf1[pb][jp * 2][0], dB1 + off);
                    ldm_x4(&bf2[pb][jp * 2][0], dB2 + off);
                }
            };

            ldfr(0, 0);
#pragma unroll
            for (int ks = 0; ks < 4; ks++) {
                const int cur = ks & 1;
                if (ks < 3) ldfr(ks + 1, cur ^ 1);
#pragma unroll
                for (int i = 0; i < 4; i++)
#pragma unroll
                    for (int j = 0; j < 4; j++) {
                        mma16(ah[i][j], af[cur][i], bf1[cur][j]);
                        mma16(ag[i][j], af[cur][i], bf2[cur][j]);
                    }
            }
            FENCE_ASYNC();                               // order reads before next TMA
            mbar_arrive(sb + 24 + (uint32_t)cbuf * 8);   // buffer consumed
        }

        // epilogue: og = h16((h+b1)*silu(g+bg)) -> one packed half block (b2 = nt)
        const int e = tile >> 10, nt = (tile >> 4) & 63, mtt = tile & 15;
        const float* bp1 = bias1 + (size_t)e * HH + nt * 64;
        const float* bpg = biasg + (size_t)e * HH + nt * 64;
        char* blk = (char*)(g_A2p + (((size_t)(e * 16 + mtt) * 64 + nt) << 13));
#pragma unroll
        for (int i = 0; i < 4; i++)
#pragma unroll
            for (int j = 0; j < 4; j++) {
                int kh = wc * 32 + j * 8 + 2 * tig;   // col within 64-wide tile
                float bh0 = bp1[kh], bh1 = bp1[kh + 1];
                float bg0 = bpg[kh], bg1 = bpg[kh + 1];
#pragma unroll
                for (int half = 0; half < 2; half++) {
                    int rl = wr * 64 + i * 16 + gid + half * 8;
                    float h0 = ah[i][j][2 * half]     + bh0;
                    float h1 = ah[i][j][2 * half + 1] + bh1;
                    float g0 = ag[i][j][2 * half]     + bg0;
                    float g1 = ag[i][j][2 * half + 1] + bg1;
                    uint32_t u = h2u(__floats2half2_rn(h0 * my_silu(g0), h1 * my_silu(g1)));
                    *reinterpret_cast<uint32_t*>(
                        blk + swz128((uint32_t)(rl * 128 + kh * 2))) = u;
                }
            }
#pragma unroll
        for (int i = 0; i < 4; i++)
#pragma unroll
            for (int j = 0; j < 4; j++)
#pragma unroll
                for (int k2 = 0; k2 < 4; k2++) { ah[i][j][k2] = 0.f; ag[i][j][k2] = 0.f; }

        __syncthreads();
        tile = sm_next;
        __syncthreads();
    }
}

// =================================================================================
// GEMM2 (persistent + dynamic tiles + split barriers + proxy-fenced release)
// CTA 128x128, 256 thr, f16 m16n8k16, Kc=64 -> 64 stages/tile, 3-ring, occ 2.
// =================================================================================
#define G2_STG_B 32768
#define G2_SMEM (1024 + 3 * G2_STG_B)
#define NT2 (EE * 16 * 8)

__global__ void __launch_bounds__(256, 2)
gemm2_kernel(const float* __restrict__ bias2, float* __restrict__ out) {
    extern __shared__ float sm[];
    __shared__ int sm_next;
    const uint32_t sb = smem_u32(sm);
    const int tid = threadIdx.x, wid = tid >> 5, lane = tid & 31;
    const int gid = lane >> 2, tig = lane & 3;
    const int wr = wid >> 2, wc = wid & 3;

    const int mq = lane >> 3, lr = lane & 7;
    const int rA = (mq & 1) * 8 + lr,  cA = (mq >> 1) * 16;
    const int rB = (mq >> 1) * 8 + lr, cB = (mq & 1) * 16;

    float acc[4][4][4] = {};

    auto fill = [&](int tile_, int stg, int fb) {
        const int e = tile_ >> 7, nt = (tile_ >> 4) & 7, mtt = tile_ & 15;
        const __half* aS = g_A2p + (((size_t)(e * 16 + mtt) * 64 + stg) << 13);
        const __half* bS = g_B2p + (((size_t)(e * 8  + nt) * 64 + stg) << 13);
        const uint32_t mb = sb + (uint32_t)fb * 8;
        const uint32_t dst = sb + 1024 + (uint32_t)fb * G2_STG_B;
        mbar_expect_tx(mb, G2_STG_B);
        bulk_g2s(dst,         aS, 16384, mb);
        bulk_g2s(dst + 16384, bS, 16384, mb);
    };

    if (tid == 0) {
#pragma unroll
        for (int b = 0; b < 3; b++) { mbar_init(sb + b * 8, 1); mbar_init(sb + 24 + b * 8, 256); }
        sm_next = atomicAdd(&g_ctr2, 1);
        FENCE_ASYNC();
    }
    __syncthreads();
    int tile = sm_next;
    __syncthreads();

    int pnext = NT2;
    if (tid == 0 && tile < NT2) {
        mbar_wait(sb + 24, 1); fill(tile, 0, 0);      // fresh: passes
        mbar_wait(sb + 32, 1); fill(tile, 1, 1);
    }

    int gs = 0, cb = 0, cph = 0;
#pragma unroll 1
    while (tile < NT2) {
#pragma unroll 1
        for (int s = 0; s < 64; s++, gs++) {
            if (tid == 0) {
                if (s == 0) { pnext = atomicAdd(&g_ctr2, 1); sm_next = pnext; }
                int fs = s + 2;
                int ft = (fs >= 64) ? pnext : tile;
                if (ft < NT2) {
                    int fgs = gs + 2;
                    int fj = fgs / 3, fb = fgs - 3 * fj;
                    mbar_wait(sb + 24 + (uint32_t)fb * 8, (uint32_t)((fj & 1) ^ 1));
                    fill(ft, fs & 63, fb);
                }
            }
            const int cbuf = cb;
            mbar_wait(sb + (uint32_t)cbuf * 8, (uint32_t)cph);
            if (++cb == 3) { cb = 0; cph ^= 1; }

            const uint32_t dA = sb + 1024 + (uint32_t)cbuf * G2_STG_B;
            const uint32_t dB = dA + 16384;

#pragma unroll
            for (int ks = 0; ks < 4; ks++) {
                uint32_t af[4][4], bf[4][2];
#pragma unroll
                for (int i = 0; i < 4; i++) {
                    int row = wr * 64 + i * 16 + rA;
                    uint32_t ad = dA + (uint32_t)row * 128
                                + (uint32_t)((ks * 32 + cA) ^ ((row & 7) << 4));
                    ldm_x4(af[i], ad);
                }
#pragma unroll
                for (int jp = 0; jp < 2; jp++) {
                    int n = wc * 32 + jp * 16 + rB;
                    uint32_t ad = dB + (uint32_t)n * 128
                                + (uint32_t)((ks * 32 + cB) ^ ((n & 7) << 4));
                    ldm_x4(&bf[jp * 2][0], ad);
                }
#pragma unroll
                for (int i = 0; i < 4; i++)
#pragma unroll
                    for (int j = 0; j < 4; j++)
                        mma16(acc[i][j], af[i], bf[j]);
            }
            FENCE_ASYNC();                               // order reads before next TMA
            mbar_arrive(sb + 24 + (uint32_t)cbuf * 8);
        }

        const int e = tile >> 7, nt = (tile >> 4) & 7, mtt = tile & 15;
        const int m0 = mtt * 128 + wr * 64;
        const int n0 = nt * 128 + wc * 32;
        const float* bp2 = bias2 + (size_t)e * DD;
#pragma unroll
        for (int i = 0; i < 4; i++)
#pragma unroll
            for (int j = 0; j < 4; j++) {
                int col = n0 + j * 8 + 2 * tig;
                float b0 = bp2[col], b1 = bp2[col + 1];
#pragma unroll
                for (int half = 0; half < 2; half++) {
                    int row = m0 + i * 16 + gid + half * 8;
                    float2 v = make_float2(acc[i][j][2 * half] + b0, acc[i][j][2 * half + 1] + b1);
                    *reinterpret_cast<float2*>(out + ((size_t)e * TT + row) * DD + col) = v;
                }
            }
#pragma unroll
        for (int i = 0; i < 4; i++)
#pragma unroll
            for (int j = 0; j < 4; j++)
#pragma unroll
                for (int k2 = 0; k2 < 4; k2++) acc[i][j][k2] = 0.f;

        __syncthreads();
        tile = sm_next;
        __syncthreads();
    }
}

// ---------------- launch ---------------------------------------------------------
extern "C" void kernel_launch(void* const* d_in, const int* in_sizes, int n_in,
                              void* d_out, int out_size) {
    const float* x  = (const float*)d_in[0];
    const float* w1 = (const float*)d_in[1];
    const float* b1 = (const float*)d_in[2];
    const float* wg = (const float*)d_in[3];
    const float* bg = (const float*)d_in[4];
    const float* w2 = (const float*)d_in[5];
    const float* b2 = (const float*)d_in[6];
    float* out = (float*)d_out;

    cudaFuncSetAttribute(gemm1_kernel, cudaFuncAttributeMaxDynamicSharedMemorySize, G1_SMEM);
    cudaFuncSetAttribute(gemm2_kernel, cudaFuncAttributeMaxDynamicSharedMemorySize, G2_SMEM);

    int smc = 0;
    if (cudaDeviceGetAttribute(&smc, cudaDevAttrMultiProcessorCount, 0) != cudaSuccess || smc <= 0)
        smc = 148;

    static cudaStream_t s_side = nullptr;
    static cudaEvent_t ev_fork = nullptr, ev_join = nullptr;
    if (s_side == nullptr) {
        cudaStreamCreateWithFlags(&s_side, cudaStreamNonBlocking);
        cudaEventCreateWithFlags(&ev_fork, cudaEventDisableTiming);
        cudaEventCreateWithFlags(&ev_join, cudaEventDisableTiming);
    }

    prep_a_kernel<<<PK_NX + 2 * PK_NW, 256>>>(x, w1, wg);

    cudaEventRecord(ev_fork, 0);
    cudaStreamWaitEvent(s_side, ev_fork, 0);
    prep_b_kernel<<<PK_NW, 256, 0, s_side>>>(w2);

    gemm1_kernel<<<2 * smc, 128, G1_SMEM>>>(b1, bg);      // persistent, occ 2

    cudaEventRecord(ev_join, s_side);
    cudaStreamWaitEvent(0, ev_join, 0);
    gemm2_kernel<<<2 * smc, 256, G2_SMEM>>>(b2, out);     // persistent, occ 2
}

// round 16
// speedup vs baseline: 1.0026x; 1.0026x over previous
#include <cuda_runtime.h>
#include <cuda_fp16.h>
#include <cstdint>

#define EE 8
#define TT 2048
#define DD 1024
#define HH 4096

// ---------------- packed half scratch (pre-swizzled 16KB [128 x 64h] blocks) ---
__device__ __align__(1024) __half g_A1p[(size_t)EE * TT * DD];
__device__ __align__(1024) __half g_B1p[(size_t)EE * HH * DD];
__device__ __align__(1024) __half g_Bgp[(size_t)EE * HH * DD];
__device__ __align__(1024) __half g_B2p[(size_t)EE * DD * HH];
__device__ __align__(1024) __half g_A2p[(size_t)EE * TT * HH];

__device__ int g_ctr1, g_ctr2;       // dynamic tile counters (reset by prep_a)

// ---------------- helpers ------------------------------------------------------
__device__ __forceinline__ uint32_t smem_u32(const void* p) {
    uint32_t a;
    asm("{ .reg .u64 t; cvta.to.shared.u64 t, %1; cvt.u32.u64 %0, t; }" : "=r"(a) : "l"(p));
    return a;
}
__device__ __forceinline__ uint32_t swz128(uint32_t o) { return o ^ ((o >> 3) & 0x70); }

__device__ __forceinline__ void mbar_init(uint32_t m, uint32_t c) {
    asm volatile("mbarrier.init.shared.b64 [%0], %1;" :: "r"(m), "r"(c) : "memory");
}
__device__ __forceinline__ void mbar_expect_tx(uint32_t m, uint32_t bytes) {
    asm volatile("mbarrier.arrive.expect_tx.shared.b64 _, [%0], %1;"
                 :: "r"(m), "r"(bytes) : "memory");
}
__device__ __forceinline__ void mbar_arrive(uint32_t m) {
    asm volatile("mbarrier.arrive.shared.b64 _, [%0];" :: "r"(m) : "memory");
}
__device__ __forceinline__ void mbar_wait(uint32_t m, uint32_t parity) {
    asm volatile(
        "{\n\t.reg .pred P;\n"
        "LW_%=:\n\t"
        "mbarrier.try_wait.parity.acquire.cta.shared::cta.b64 P, [%0], %1, 0x989680;\n\t"
        "@P bra.uni LD_%=;\n\t"
        "bra.uni LW_%=;\n"
        "LD_%=:\n\t}"
        :: "r"(m), "r"(parity) : "memory");
}
__device__ __forceinline__ void bulk_g2s(uint32_t dst, const void* src,
                                         uint32_t bytes, uint32_t mbar) {
    asm volatile(
        "cp.async.bulk.shared::cluster.global.mbarrier::complete_tx::bytes "
        "[%0], [%1], %2, [%3];"
        :: "r"(dst), "l"(src), "r"(bytes), "r"(mbar) : "memory");
}
__device__ __forceinline__ void bulk_s2g(void* dst, uint32_t src, uint32_t bytes) {
    asm volatile("cp.async.bulk.global.shared::cta.bulk_group [%0], [%1], %2;"
                 :: "l"(dst), "r"(src), "r"(bytes) : "memory");
}
#define BULK_COMMIT()     asm volatile("cp.async.bulk.commit_group;" ::: "memory")
#define BULK_WAIT_READ()  asm volatile("cp.async.bulk.wait_group.read 0;" ::: "memory")
#define BULK_WAIT_ALL()   asm volatile("cp.async.bulk.wait_group 0;" ::: "memory")
#define FENCE_ASYNC() asm volatile("fence.proxy.async.shared::cta;" ::: "memory")

__device__ __forceinline__ void sts32(uint32_t addr, uint32_t v) {
    asm volatile("st.shared.b32 [%0], %1;" :: "r"(addr), "r"(v) : "memory");
}
__device__ __forceinline__ void ldm_x4(uint32_t* r, uint32_t addr) {
    asm volatile("ldmatrix.sync.aligned.m8n8.x4.shared.b16 {%0,%1,%2,%3}, [%4];"
                 : "=r"(r[0]), "=r"(r[1]), "=r"(r[2]), "=r"(r[3]) : "r"(addr));
}
__device__ __forceinline__ void mma16(float* c, const uint32_t* a, const uint32_t* b) {
    asm volatile(
        "mma.sync.aligned.m16n8k16.row.col.f32.f16.f16.f32 "
        "{%0,%1,%2,%3}, {%4,%5,%6,%7}, {%8,%9}, {%0,%1,%2,%3};"
        : "+f"(c[0]), "+f"(c[1]), "+f"(c[2]), "+f"(c[3])
        : "r"(a[0]), "r"(a[1]), "r"(a[2]), "r"(a[3]), "r"(b[0]), "r"(b[1]));
}
__device__ __forceinline__ float my_silu(float g) { return g / (1.0f + __expf(-g)); }
__device__ __forceinline__ uint32_t h2u(__half2 h) { return *reinterpret_cast<uint32_t*>(&h); }

// ---------------- shared transpose tile body ------------------------------------
__device__ __forceinline__ void transpose_tile(const float* __restrict__ in,
                                               __half* __restrict__ out,
                                               int R, int C, int b, int tid,
                                               __half* tsm /* 128*66 halves */) {
    const int NTc = C >> 7, NKB = R >> 6;
    const int nt = b % NTc;
    const int kb = (b / NTc) % NKB;
    const int e  = b / (NTc * NKB);

    const float* ip = in + (size_t)e * R * C + (size_t)(kb * 64) * C + nt * 128;

    const int warp = tid >> 5, cl = tid & 31;
#pragma unroll
    for (int it = 0; it < 4; it++) {
        int kr = (warp + 8 * it) * 2;
        float4 v0 = *reinterpret_cast<const float4*>(ip + (size_t)kr * C + 4 * cl);
        float4 v1 = *reinterpret_cast<const float4*>(ip + (size_t)(kr + 1) * C + 4 * cl);
        const float* f0 = &v0.x;
        const float* f1 = &v1.x;
#pragma unroll
        for (int j = 0; j < 4; j++) {
            __half2 h = __floats2half2_rn(f0[j], f1[j]);
            *reinterpret_cast<__half2*>(&tsm[(4 * cl + j) * 66 + kr]) = h;
        }
    }
    __syncthreads();

    char* bp = (char*)(out + (((size_t)(e * NTc + nt) * NKB + kb) << 13));
    const int kc = tid & 7, nlb = tid >> 3;
#pragma unroll
    for (int it = 0; it < 4; it++) {
        int nl = nlb + 32 * it;
        const uint32_t* rowp = reinterpret_cast<const uint32_t*>(&tsm[nl * 66 + kc * 8]);
        uint4 u;
        u.x = rowp[0]; u.y = rowp[1]; u.z = rowp[2]; u.w = rowp[3];
        *reinterpret_cast<uint4*>(bp + swz128((uint32_t)(nl * 128 + kc * 16))) = u;
    }
}

// =================================================================================
// PREP A (critical path): pack x + transpose w1, wg + counter reset
// =================================================================================
#define PK_NX 16384
#define PK_NW 4096

__global__ void __launch_bounds__(256, 6)
prep_a_kernel(const float* __restrict__ x, const float* __restrict__ w1,
              const float* __restrict__ wg) {
    const int tid = threadIdx.x;
    int b = blockIdx.x;

    if (b == 0 && tid == 0) { g_ctr1 = 0; g_ctr2 = 0; }

    if (b < PK_NX) {                                   // ---- pack x ----
        size_t idx = ((size_t)b * 256 + tid) * 4;
        float4 v = *reinterpret_cast<const float4*>(x + idx);
        int d = (int)(idx & (DD - 1));
        int t = (int)((idx / DD) & (TT - 1));
        int e = (int)(idx / ((size_t)TT * DD));
        int mt = t >> 7, r = t & 127, bd = d >> 6, c = d & 63;
        char* blk = (char*)(g_A1p + (((size_t)(e * 16 + mt) * 16 + bd) << 13));
        uint2 u;
        u.x = h2u(__floats2half2_rn(v.x, v.y));
        u.y = h2u(__floats2half2_rn(v.z, v.w));
        *reinterpret_cast<uint2*>(blk + swz128((uint32_t)(r * 128 + c * 2))) = u;
        return;
    }

    __shared__ __half tsm[128 * 66];
    b -= PK_NX;
    if (b < PK_NW) transpose_tile(w1, g_B1p, DD, HH, b, tid, tsm);
    else           transpose_tile(wg, g_Bgp, DD, HH, b - PK_NW, tid, tsm);
}

// =================================================================================
// PREP B (overlapped with GEMM1): transpose w2
// =================================================================================
__global__ void __launch_bounds__(256, 6)
prep_b_kernel(const float* __restrict__ w2) {
    __shared__ __half tsm[128 * 66];
    transpose_tile(w2, g_B2p, HH, DD, blockIdx.x, threadIdx.x, tsm);
}

// =================================================================================
// GEMM1 fused (persistent + dynamic tiles + split barriers), R14 shape + staged
// epilogue: og written to a 32KB smem staging area (conflict-free STS) and drained
// by ONE cp.async.bulk smem->global per tile, overlapped with next tile's mainloop.
// CTA 128x128 dual-plane, 256 thr, f16 m16n8k16, Kc=128, 2-stage ring (96KB/stage).
// smem: mbars 1KB | ring 192KB | staging 32KB = 230400 B (occ 1).
// =================================================================================
#define G1_STG_B 98304
#define G1_SMEM (1024 + 2 * G1_STG_B + 32768)
#define NT1 (EE * 16 * 32)

__global__ void __launch_bounds__(256, 1)
gemm1_kernel(const float* __restrict__ bias1, const float* __restrict__ biasg) {
    extern __shared__ float sm[];
    __shared__ int sm_next;
    const uint32_t sb = smem_u32(sm);
    const uint32_t stg = sb + 1024 + 2 * G1_STG_B;    // epilogue staging (32KB)
    const int tid = threadIdx.x, wid = tid >> 5, lane = tid & 31;
    const int gid = lane >> 2, tig = lane & 3;
    const int wr = wid >> 2, wc = wid & 3;

    const int mq = lane >> 3, lr = lane & 7;
    const int rA = (mq & 1) * 8 + lr,  cA = (mq >> 1) * 16;
    const int rB = (mq >> 1) * 8 + lr, cB = (mq & 1) * 16;

    float ah[4][4][4] = {}, ag[4][4][4] = {};

    auto fill = [&](int tile_, int stgi, int fb) {
        const int e = tile_ >> 9, nt = (tile_ >> 4) & 31, mtt = tile_ & 15;
        const __half* aS  = g_A1p + (((size_t)(e * 16 + mtt) * 16 + 2 * stgi) << 13);
        const __half* b1S = g_B1p + (((size_t)(e * 32 + nt) * 16 + 2 * stgi) << 13);
        const __half* bgS = g_Bgp + (((size_t)(e * 32 + nt) * 16 + 2 * stgi) << 13);
        const uint32_t mb = sb + (uint32_t)fb * 8;
        const uint32_t dst = sb + 1024 + (uint32_t)fb * G1_STG_B;
        mbar_expect_tx(mb, G1_STG_B);
        bulk_g2s(dst,          aS,  32768, mb);
        bulk_g2s(dst + 32768,  b1S, 32768, mb);
        bulk_g2s(dst + 65536,  bgS, 32768, mb);
    };

    if (tid == 0) {
        mbar_init(sb, 1);       mbar_init(sb + 8, 1);
        mbar_init(sb + 16, 256); mbar_init(sb + 24, 256);
        sm_next = atomicAdd(&g_ctr1, 1);
        FENCE_ASYNC();
    }
    __syncthreads();
    int tile = sm_next;
    __syncthreads();                                  // all read before tid0 rewrites

    int pnext = NT1;                                  // producer-only state (tid0)
    if (tid == 0 && tile < NT1) {
        mbar_wait(sb + 16, 1);                        // fresh: passes
        fill(tile, 0, 0);
    }

    int gs = 0;
#pragma unroll 1
    while (tile < NT1) {
#pragma unroll 1
        for (int s = 0; s < 8; s++, gs++) {
            if (tid == 0) {
                if (s == 0) { pnext = atomicAdd(&g_ctr1, 1); sm_next = pnext; }
                int ft = (s == 7) ? pnext : tile;
                if (ft < NT1) {
                    int fgs = gs + 1, fb = fgs & 1;
                    mbar_wait(sb + 16 + (uint32_t)fb * 8, ((fgs >> 1) & 1) ^ 1);
                    fill(ft, (s + 1) & 7, fb);
                }
            }
            const int cbuf = gs & 1;
            mbar_wait(sb + (uint32_t)cbuf * 8, (gs >> 1) & 1);

            const uint32_t dA  = sb + 1024 + (uint32_t)cbuf * G1_STG_B;
            const uint32_t dB1 = dA + 32768;
            const uint32_t dB2 = dA + 65536;

            uint32_t af[2][4][4], bf1[2][4][2], bf2[2][4][2];

            auto ldfr = [&](int ks, int pb) {
                const int kk = ks & 3;
                const uint32_t blk = (uint32_t)(ks >> 2) * 16384;
#pragma unroll
                for (int i = 0; i < 4; i++) {
                    int row = wr * 64 + i * 16 + rA;
                    uint32_t ad = dA + blk + (uint32_t)row * 128
                                + (uint32_t)((kk * 32 + cA) ^ ((row & 7) << 4));
                    ldm_x4(af[pb][i], ad);
                }
#pragma unroll
                for (int jp = 0; jp < 2; jp++) {
                    int n = wc * 32 + jp * 16 + rB;
                    uint32_t off = blk + (uint32_t)n * 128
                                 + (uint32_t)((kk * 32 + cB) ^ ((n & 7) << 4));
                    ldm_x4(&bf1[pb][jp * 2][0], dB1 + off);
                    ldm_x4(&bf2[pb][jp * 2][0], dB2 + off);
                }
            };

            ldfr(0, 0);
#pragma unroll
            for (int ks = 0; ks < 8; ks++) {
                const int cur = ks & 1;
                if (ks < 7) ldfr(ks + 1, cur ^ 1);
#pragma unroll
                for (int i = 0; i < 4; i++)
#pragma unroll
                    for (int j = 0; j < 4; j++) {
                        mma16(ah[i][j], af[cur][i], bf1[cur][j]);
                        mma16(ag[i][j], af[cur][i], bf2[cur][j]);
                    }
            }
            FENCE_ASYNC();                               // order reads before next TMA
            mbar_arrive(sb + 16 + (uint32_t)cbuf * 8);   // buffer consumed
        }

        // ---- staged epilogue: og -> smem staging -> one 32KB bulk store ----
        const int e = tile >> 9, nt = (tile >> 4) & 31, mtt = tile & 15;
        const float* bp1 = bias1 + (size_t)e * HH + nt * 128;
        const float* bpg = biasg + (size_t)e * HH + nt * 128;

        if (tid == 0) BULK_WAIT_READ();               // staging free (prev tile drained)
        __syncthreads();

        const uint32_t sdst = stg + (uint32_t)(wc >> 1) * 16384;
#pragma unroll
        for (int i = 0; i < 4; i++)
#pragma unroll
            for (int j = 0; j < 4; j++) {
                int cl = wc * 32 + j * 8 + 2 * tig;
                float bh0 = bp1[cl], bh1 = bp1[cl + 1];
                float bg0 = bpg[cl], bg1 = bpg[cl + 1];
                int kh = (wc & 1) * 32 + j * 8 + 2 * tig;
#pragma unroll
                for (int half = 0; half < 2; half++) {
                    int rl = wr * 64 + i * 16 + gid + half * 8;
                    float h0 = ah[i][j][2 * half]     + bh0;
                    float h1 = ah[i][j][2 * half + 1] + bh1;
                    float g0 = ag[i][j][2 * half]     + bg0;
                    float g1 = ag[i][j][2 * half + 1] + bg1;
                    uint32_t u = h2u(__floats2half2_rn(h0 * my_silu(g0), h1 * my_silu(g1)));
                    sts32(sdst + swz128((uint32_t)(rl * 128 + kh * 2)), u);
                }
            }
        __syncthreads();
        if (tid == 0) {
            FENCE_ASYNC();                             // STS visible to async proxy
            char* gdst = (char*)(g_A2p + (((size_t)(e * 16 + mtt) * 64 + nt * 2) << 13));
            bulk_s2g(gdst, stg, 32768);
            BULK_COMMIT();
        }
#pragma unroll
        for (int i = 0; i < 4; i++)
#pragma unroll
            for (int j = 0; j < 4; j++)
#pragma unroll
                for (int k2 = 0; k2 < 4; k2++) { ah[i][j][k2] = 0.f; ag[i][j][k2] = 0.f; }

        __syncthreads();
        tile = sm_next;
        __syncthreads();
    }
    if (tid == 0) BULK_WAIT_ALL();                    // og globally visible at exit
}

// =================================================================================
// GEMM2 (persistent + dynamic tiles + split barriers + proxy-fenced release)
// CTA 128x128, 256 thr, f16 m16n8k16, Kc=64 -> 64 stages/tile, 3-ring, occ 2.
// =================================================================================
#define G2_STG_B 32768
#define G2_SMEM (1024 + 3 * G2_STG_B)
#define NT2 (EE * 16 * 8)

__global__ void __launch_bounds__(256, 2)
gemm2_kernel(const float* __restrict__ bias2, float* __restrict__ out) {
    extern __shared__ float sm[];
    __shared__ int sm_next;
    const uint32_t sb = smem_u32(sm);
    const int tid = threadIdx.x, wid = tid >> 5, lane = tid & 31;
    const int gid = lane >> 2, tig = lane & 3;
    const int wr = wid >> 2, wc = wid & 3;

    const int mq = lane >> 3, lr = lane & 7;
    const int rA = (mq & 1) * 8 + lr,  cA = (mq >> 1) * 16;
    const int rB = (mq >> 1) * 8 + lr, cB = (mq & 1) * 16;

    float acc[4][4][4] = {};

    auto fill = [&](int tile_, int stg, int fb) {
        const int e = tile_ >> 7, nt = (tile_ >> 4) & 7, mtt = tile_ & 15;
        const __half* aS = g_A2p + (((size_t)(e * 16 + mtt) * 64 + stg) << 13);
        const __half* bS = g_B2p + (((size_t)(e * 8  + nt) * 64 + stg) << 13);
        const uint32_t mb = sb + (uint32_t)fb * 8;
        const uint32_t dst = sb + 1024 + (uint32_t)fb * G2_STG_B;
        mbar_expect_tx(mb, G2_STG_B);
        bulk_g2s(dst,         aS, 16384, mb);
        bulk_g2s(dst + 16384, bS, 16384, mb);
    };

    if (tid == 0) {
#pragma unroll
        for (int b = 0; b < 3; b++) { mbar_init(sb + b * 8, 1); mbar_init(sb + 24 + b * 8, 256); }
        sm_next = atomicAdd(&g_ctr2, 1);
        FENCE_ASYNC();
    }
    __syncthreads();
    int tile = sm_next;
    __syncthreads();

    int pnext = NT2;
    if (tid == 0 && tile < NT2) {
        mbar_wait(sb + 24, 1); fill(tile, 0, 0);      // fresh: passes
        mbar_wait(sb + 32, 1); fill(tile, 1, 1);
    }

    int gs = 0, cb = 0, cph = 0;
#pragma unroll 1
    while (tile < NT2) {
#pragma unroll 1
        for (int s = 0; s < 64; s++, gs++) {
            if (tid == 0) {
                if (s == 0) { pnext = atomicAdd(&g_ctr2, 1); sm_next = pnext; }
                int fs = s + 2;
                int ft = (fs >= 64) ? pnext : tile;
                if (ft < NT2) {
                    int fgs = gs + 2;
                    int fj = fgs / 3, fb = fgs - 3 * fj;
                    mbar_wait(sb + 24 + (uint32_t)fb * 8, (uint32_t)((fj & 1) ^ 1));
                    fill(ft, fs & 63, fb);
                }
            }
            const int cbuf = cb;
            mbar_wait(sb + (uint32_t)cbuf * 8, (uint32_t)cph);
            if (++cb == 3) { cb = 0; cph ^= 1; }

            const uint32_t dA = sb + 1024 + (uint32_t)cbuf * G2_STG_B;
            const uint32_t dB = dA + 16384;

#pragma unroll
            for (int ks = 0; ks < 4; ks++) {
                uint32_t af[4][4], bf[4][2];
#pragma unroll
                for (int i = 0; i < 4; i++) {
                    int row = wr * 64 + i * 16 + rA;
                    uint32_t ad = dA + (uint32_t)row * 128
                                + (uint32_t)((ks * 32 + cA) ^ ((row & 7) << 4));
                    ldm_x4(af[i], ad);
                }
#pragma unroll
                for (int jp = 0; jp < 2; jp++) {
                    int n = wc * 32 + jp * 16 + rB;
                    uint32_t ad = dB + (uint32_t)n * 128
                                + (uint32_t)((ks * 32 + cB) ^ ((n & 7) << 4));
                    ldm_x4(&bf[jp * 2][0], ad);
                }
#pragma unroll
                for (int i = 0; i < 4; i++)
#pragma unroll
                    for (int j = 0; j < 4; j++)
                        mma16(acc[i][j], af[i], bf[j]);
            }
            FENCE_ASYNC();                               // order reads before next TMA
            mbar_arrive(sb + 24 + (uint32_t)cbuf * 8);
        }

        const int e = tile >> 7, nt = (tile >> 4) & 7, mtt = tile & 15;
        const int m0 = mtt * 128 + wr * 64;
        const int n0 = nt * 128 + wc * 32;
        const float* bp2 = bias2 + (size_t)e * DD;
#pragma unroll
        for (int i = 0; i < 4; i++)
#pragma unroll
            for (int j = 0; j < 4; j++) {
                int col = n0 + j * 8 + 2 * tig;
                float b0 = bp2[col], b1 = bp2[col + 1];
#pragma unroll
                for (int half = 0; half < 2; half++) {
                    int row = m0 + i * 16 + gid + half * 8;
                    float2 v = make_float2(acc[i][j][2 * half] + b0, acc[i][j][2 * half + 1] + b1);
                    *reinterpret_cast<float2*>(out + ((size_t)e * TT + row) * DD + col) = v;
                }
            }
#pragma unroll
        for (int i = 0; i < 4; i++)
#pragma unroll
            for (int j = 0; j < 4; j++)
#pragma unroll
                for (int k2 = 0; k2 < 4; k2++) acc[i][j][k2] = 0.f;

        __syncthreads();
        tile = sm_next;
        __syncthreads();
    }
}

// ---------------- launch ---------------------------------------------------------
extern "C" void kernel_launch(void* const* d_in, const int* in_sizes, int n_in,
                              void* d_out, int out_size) {
    const float* x  = (const float*)d_in[0];
    const float* w1 = (const float*)d_in[1];
    const float* b1 = (const float*)d_in[2];
    const float* wg = (const float*)d_in[3];
    const float* bg = (const float*)d_in[4];
    const float* w2 = (const float*)d_in[5];
    const float* b2 = (const float*)d_in[6];
    float* out = (float*)d_out;

    cudaFuncSetAttribute(gemm1_kernel, cudaFuncAttributeMaxDynamicSharedMemorySize, G1_SMEM);
    cudaFuncSetAttribute(gemm2_kernel, cudaFuncAttributeMaxDynamicSharedMemorySize, G2_SMEM);

    int smc = 0;
    if (cudaDeviceGetAttribute(&smc, cudaDevAttrMultiProcessorCount, 0) != cudaSuccess || smc <= 0)
        smc = 148;

    static cudaStream_t s_side = nullptr;
    static cudaEvent_t ev_fork = nullptr, ev_join = nullptr;
    if (s_side == nullptr) {
        cudaStreamCreateWithFlags(&s_side, cudaStreamNonBlocking);
        cudaEventCreateWithFlags(&ev_fork, cudaEventDisableTiming);
        cudaEventCreateWithFlags(&ev_join, cudaEventDisableTiming);
    }

    prep_a_kernel<<<PK_NX + 2 * PK_NW, 256>>>(x, w1, wg);

    cudaEventRecord(ev_fork, 0);
    cudaStreamWaitEvent(s_side, ev_fork, 0);
    prep_b_kernel<<<PK_NW, 256, 0, s_side>>>(w2);

    gemm1_kernel<<<smc, 256, G1_SMEM>>>(b1, bg);          // persistent, staged epilogue

    cudaEventRecord(ev_join, s_side);
    cudaStreamWaitEvent(0, ev_join, 0);
    gemm2_kernel<<<2 * smc, 256, G2_SMEM>>>(b2, out);     // persistent, occ 2
}